// round 8
// baseline (speedup 1.0000x reference)
#include <cuda_runtime.h>
#include <cfloat>

// Reverse cummax along axis 1 of [B=16, H=128, W=128, C=256] fp32.
// One thread per (b, w, c4) float4-column; walk h backward with running max.
//
// FINAL (R3 configuration — empirical optimum over 6 rounds):
//   - 128-thread CTAs x 1024 blocks: balanced 7 CTAs/SM (the 256thr/512CTA
//     variant suffered a 4-vs-3 CTA/SM imbalance costing ~5% DRAM BW).
//   - Simple interleaved unroll-4 body; ptxas schedules the LDG.128 batch
//     ahead of the FMNMX chain itself (explicit batching/unroll-8: neutral).
//   - DEFAULT cache policy: loads+stores hit the same lines; __ldcs/__stcs
//     evict-first broke read-fill/dirty-write coalescing in LTS (-30%).
// Achieves 6.2 TB/s (78% of HBM spec) = measured ceiling for 1:1 r/w
// streaming on this part; kernel is hard HBM-bound (issue 5%, fma 0.3%).

static constexpr int B = 16;
static constexpr int H = 128;
static constexpr int W = 128;
static constexpr int C = 256;
static constexpr int C4 = C / 4;            // 64 float4 per row
static constexpr int STRIDE_H = W * C4;     // 8192 float4 between h slices
static constexpr int COLS = B * W * C4;     // 131072 columns
static constexpr int PER_B = W * C4;        // 8192 columns per batch
static constexpr long PER_B_ELEMS = (long)H * W * C4;

__global__ void __launch_bounds__(128) rev_cummax_kernel(
    const float4* __restrict__ in, float4* __restrict__ out)
{
    int col = blockIdx.x * blockDim.x + threadIdx.x;

    int b   = col >> 13;            // col / 8192
    int rem = col & (PER_B - 1);
    long base = (long)b * PER_B_ELEMS + rem;

    float4 m = make_float4(-FLT_MAX, -FLT_MAX, -FLT_MAX, -FLT_MAX);

    #pragma unroll 4
    for (int h = H - 1; h >= 0; --h) {
        long idx = base + (long)h * STRIDE_H;
        float4 v = in[idx];
        m.x = fmaxf(m.x, v.x);
        m.y = fmaxf(m.y, v.y);
        m.z = fmaxf(m.z, v.z);
        m.w = fmaxf(m.w, v.w);
        out[idx] = m;
    }
}

extern "C" void kernel_launch(void* const* d_in, const int* in_sizes, int n_in,
                              void* d_out, int out_size)
{
    (void)in_sizes; (void)n_in; (void)out_size;
    const float4* in  = (const float4*)d_in[0];
    float4*       out = (float4*)d_out;

    const int threads = 128;
    const int blocks  = COLS / threads;  // 1024, exact
    rev_cummax_kernel<<<blocks, threads>>>(in, out);
}

// round 9
// speedup vs baseline: 1.0053x; 1.0053x over previous
#include <cuda_runtime.h>
#include <cfloat>

// Reverse cummax along axis 1 of [B=16, H=128, W=128, C=256] fp32.
// One thread per (b, w, c4) float4-column; walk h backward with running max.
//
// FINAL consolidation (R8):
//   - 128-thread CTAs x 1024 blocks: balanced 7 CTAs/SM.
//   - unroll-8 interleaved body (best recorded bench: 90.56us).
//   - 32-bit pointer-decrement addressing (tensor = 16.7M float4 < 2^31):
//     removes per-iteration IMAD.WIDE 64-bit index math.
//   - DEFAULT cache policy (evict-first hints measured -30%).
// Hard HBM-bound at ~6.2 TB/s (78% of spec) — the measured ceiling for
// 1:1 read/write streaming on this part.

static constexpr int B = 16;
static constexpr int H = 128;
static constexpr int W = 128;
static constexpr int C = 256;
static constexpr int C4 = C / 4;            // 64 float4 per row
static constexpr int STRIDE_H = W * C4;     // 8192 float4 between h slices
static constexpr int COLS = B * W * C4;     // 131072 columns
static constexpr int UN = 8;

__global__ void __launch_bounds__(128) rev_cummax_kernel(
    const float4* __restrict__ in, float4* __restrict__ out)
{
    // Column index == flat offset of the h=0 element of this column.
    int col = blockIdx.x * blockDim.x + threadIdx.x;
    // Top of the column (h = H-1); all offsets fit in 32 bits.
    int top = col + (H - 1) * STRIDE_H * ( (unsigned)col >> 13 == (unsigned)col >> 13 ? 1 : 1 );
    // (b * PER_B_ELEMS) decomposition is unnecessary: the tensor is dense, so
    // flat column index col in [0, COLS) maps to flat element offset
    // b*H*W*C4 + w*C4 + c4 ... but col enumerates (b, w, c4) packed WITHOUT
    // the H dimension. Recover the dense offset explicitly:
    int b   = col >> 13;                    // col / (W*C4)
    int rem = col & (W * C4 - 1);
    top = b * (H * W * C4) + rem + (H - 1) * STRIDE_H;

    const float4* p = in  + top;
    float4*       q = out + top;

    float4 m = make_float4(-FLT_MAX, -FLT_MAX, -FLT_MAX, -FLT_MAX);

    #pragma unroll 1
    for (int it = 0; it < H / UN; ++it) {
        #pragma unroll
        for (int j = 0; j < UN; ++j) {
            float4 v = p[-j * STRIDE_H];
            m.x = fmaxf(m.x, v.x);
            m.y = fmaxf(m.y, v.y);
            m.z = fmaxf(m.z, v.z);
            m.w = fmaxf(m.w, v.w);
            q[-j * STRIDE_H] = m;
        }
        p -= UN * STRIDE_H;
        q -= UN * STRIDE_H;
    }
}

extern "C" void kernel_launch(void* const* d_in, const int* in_sizes, int n_in,
                              void* d_out, int out_size)
{
    (void)in_sizes; (void)n_in; (void)out_size;
    const float4* in  = (const float4*)d_in[0];
    float4*       out = (float4*)d_out;

    const int threads = 128;
    const int blocks  = COLS / threads;  // 1024, exact
    rev_cummax_kernel<<<blocks, threads>>>(in, out);
}